// round 16
// baseline (speedup 1.0000x reference)
#include <cuda_runtime.h>
#include <cuda_fp16.h>
#include <cstdint>

// Fixed-shape problem: G=4000, B=8, DEG=32, BATCH=128
#define G_     4000
#define NB_    132000               // G*DEG + G
#define BATCH_ 128
#define D_     32000
#define CAP    128                  // per-group bin capacity (max cnt ~60)
#define NSTG   4                    // per-warp cp.async pipeline depth (pairs)
#define ROWB   80                   // bytes per row in warp tile (64B data + 16B pad)
#define STGB   (16 * ROWB)          // 1280 B per stage per warp
#define WBUF   (NSTG * STGB)        // 5120 B per warp
#define SCAT_CTAS ((NB_ + 255) / 256)    // 516 (1 element per thread)

// Scratch (no allocations allowed -> __device__ globals; zero-init on load)
__device__ int    g_cnt[G_];                      // re-zeroed by main_kernel each run
__device__ int2   g_bin[(size_t)G_ * CAP];        // (block id n, src group)
__device__ __half g_xTh[(size_t)D_ * BATCH_];     // fp16 xT[col * 128 + b]

// ---------------- fused pre-kernel: transpose (CTAs 0..3999) + bin scatter ----------

__global__ void __launch_bounds__(256) pre_kernel(const float* __restrict__ x,
                                                  const int* __restrict__ bi,
                                                  const int* __restrict__ bo) {
    int bid = blockIdx.x;
    if (bid < 4000) {
        // ---- transpose x (BATCH, D) -> fp16 xT (D, BATCH) ----
        __shared__ float tile[32][33];
        int bx = bid % 1000, by = bid / 1000;
        int c0 = bx * 32;             // along D
        int r0 = by * 32;             // along BATCH
        int tx = threadIdx.x & 31, ty = threadIdx.x >> 5;
#pragma unroll
        for (int r = 0; r < 4; r++)
            tile[ty + 8 * r][tx] = x[(size_t)(r0 + ty + 8 * r) * D_ + (c0 + tx)];
        __syncthreads();
        int t = threadIdx.x;
        int d = t >> 3;
        int bq = (t & 7) * 4;
        __half h[4];
#pragma unroll
        for (int k = 0; k < 4; k++) h[k] = __float2half_rn(tile[bq + k][d]);
        *(uint2*)&g_xTh[(size_t)(c0 + d) * BATCH_ + r0 + bq] = *(const uint2*)h;
    } else {
        // ---- direct bin scatter: 1 element per thread ----
        int i = (bid - 4000) * 256 + threadIdx.x;
        if (i >= NB_) return;
        int src = bi[i];
        int dst = bo[i];
        int p = atomicAdd(&g_cnt[dst], 1);
        g_bin[(size_t)dst * CAP + p] = make_int2(i, src);
    }
}

// ---------------- tensor-core main: warp-private cp.async pipelines ----------------

__device__ __forceinline__ void ldsm4t(uint32_t& r0, uint32_t& r1, uint32_t& r2,
                                       uint32_t& r3, uint32_t addr) {
    asm volatile("ldmatrix.sync.aligned.m8n8.x4.trans.shared.b16 {%0,%1,%2,%3}, [%4];"
                 : "=r"(r0), "=r"(r1), "=r"(r2), "=r"(r3) : "r"(addr));
}

__device__ __forceinline__ void mma16816(float* c, uint32_t a0, uint32_t a1, uint32_t a2,
                                         uint32_t a3, uint32_t b0, uint32_t b1) {
    asm volatile("mma.sync.aligned.m16n8k16.row.col.f32.f16.f16.f32 "
                 "{%0,%1,%2,%3}, {%4,%5,%6,%7}, {%8,%9}, {%0,%1,%2,%3};"
                 : "+f"(c[0]), "+f"(c[1]), "+f"(c[2]), "+f"(c[3])
                 : "r"(a0), "r"(a1), "r"(a2), "r"(a3), "r"(b0), "r"(b1));
}

__device__ __forceinline__ void cp16(uint32_t saddr, const void* gaddr) {
    asm volatile("cp.async.cg.shared.global [%0], [%1], 16;"
                 :: "r"(saddr), "l"(gaddr) : "memory");
}
__device__ __forceinline__ void cp_commit() {
    asm volatile("cp.async.commit_group;" ::: "memory");
}
template <int N>
__device__ __forceinline__ void cp_wait() {
    asm volatile("cp.async.wait_group %0;" :: "n"(N) : "memory");
}

__device__ __forceinline__ uint32_t packh2(float lo, float hi) {
    __half2 h = __halves2half2(__float2half_rn(lo), __float2half_rn(hi));
    return *(uint32_t*)&h;
}

__global__ void __launch_bounds__(128, 8) main_kernel(const float* __restrict__ x,
                                                      const float* __restrict__ w,
                                                      float* __restrict__ out) {
    __shared__ __align__(16) __half sx[4 * WBUF / 2];   // 20480 B (aliased as sred)
    __shared__ int ssrc[CAP];   // src group per block
    __shared__ int snum[CAP];   // block id n per block

    int g = blockIdx.x;
    int tid = threadIdx.x, lane = tid & 31, wid = tid >> 5;
    int cnt = g_cnt[g];
    const int2* bin = g_bin + (size_t)g * CAP;

    if (tid < cnt) {
        int2 e = bin[tid];
        snum[tid] = e.x;
        ssrc[tid] = e.y;
    }
    __syncthreads();

    int npairs = (cnt + 1) >> 1;

    uint32_t sx_u;
    asm("{ .reg .u64 t; cvta.to.shared.u64 t, %1; cvt.u32.u64 %0, t; }" : "=r"(sx_u) : "l"(sx));
    uint32_t wbase = sx_u + wid * WBUF;

    // per-lane constants
    int row1 = lane >> 2;                 // copy row within block tile (0..7)
    int quad = lane & 3;                  // 16B chunk within 64B warp row-slice
    uint32_t cpoff = (uint32_t)(row1 * ROWB + quad * 16);
    int gcol = wid * 32 + quad * 8;       // gmem column (halves)
    int r8 = lane & 7, t4 = lane >> 3;
    uint32_t boff = (uint32_t)((r8 + ((t4 & 1) << 3)) * ROWB + ((t4 >> 1) << 4));
    int gr = lane >> 2;                   // A frag: o row
    int c2 = (lane & 3) << 1;             // A frag: i col pair base
    int woff = c2 * 8 + gr;               // f32 w offset for A frag

    float acc[4][4];
#pragma unroll
    for (int q = 0; q < 4; q++)
#pragma unroll
        for (int r = 0; r < 4; r++) acc[q][r] = 0.f;

    // ---- prologue: fill the per-warp pipeline (always NSTG commits) ----
#pragma unroll
    for (int s = 0; s < NSTG; s++) {
        if (s < npairs) {
            int j0 = 2 * s;
            int s0 = ssrc[j0];
            int s1 = (j0 + 1 < cnt) ? ssrc[j0 + 1] : s0;
            uint32_t d = wbase + s * STGB + cpoff;
            cp16(d,            g_xTh + ((size_t)s0 * 8 + row1) * BATCH_ + gcol);
            cp16(d + 8 * ROWB, g_xTh + ((size_t)s1 * 8 + row1) * BATCH_ + gcol);
        }
        cp_commit();
    }

    // ---- A regs for pairs 0 and 1 ----
    uint32_t cA0 = 0, cA2 = 0, cB0 = 0, cB2 = 0;
    {
        const float* wp = w + (size_t)snum[0] * 64 + woff;
        cA0 = packh2(wp[0], wp[8]);
        if (1 < cnt) {
            const float* wq = w + (size_t)snum[1] * 64 + woff;
            cA2 = packh2(wq[0], wq[8]);
        }
        if (1 < npairs) {
            const float* wp1 = w + (size_t)snum[2] * 64 + woff;
            cB0 = packh2(wp1[0], wp1[8]);
            if (3 < cnt) {
                const float* wq1 = w + (size_t)snum[3] * 64 + woff;
                cB2 = packh2(wq1[0], wq1[8]);
            }
        }
    }

    const uint32_t zero = 0;
    int niter = (npairs + 1) >> 1;
    int st = 0;   // stage of pair 2t (pair p -> stage p & 3)
    for (int t = 0; t < niter; t++) {
        int p0 = 2 * t, p1 = 2 * t + 1;

        // prefetch A for pairs p0+2, p1+2 (8 LDGs fly under wait + compute)
        uint32_t nA0 = 0, nA2 = 0, nB0 = 0, nB2 = 0;
        {
            int pa = p0 + 2;
            if (pa < npairs) {
                const float* wp = w + (size_t)snum[2 * pa] * 64 + woff;
                nA0 = packh2(wp[0], wp[8]);
                if (2 * pa + 1 < cnt) {
                    const float* wq = w + (size_t)snum[2 * pa + 1] * 64 + woff;
                    nA2 = packh2(wq[0], wq[8]);
                }
            }
            int pb = p1 + 2;
            if (pb < npairs) {
                const float* wp = w + (size_t)snum[2 * pb] * 64 + woff;
                nB0 = packh2(wp[0], wp[8]);
                if (2 * pb + 1 < cnt) {
                    const float* wq = w + (size_t)snum[2 * pb + 1] * 64 + woff;
                    nB2 = packh2(wq[0], wq[8]);
                }
            }
        }

        cp_wait<2>();    // groups for pairs p0 and p1 complete
        __syncwarp();

        // compute pair p0 (stage st) and pair p1 (stage st^1 sequence-wise st+1)
        {
            uint32_t addr0 = wbase + st * STGB + boff;
            uint32_t b00, b01, b10, b11, b20, b21, b30, b31;
            ldsm4t(b00, b01, b10, b11, addr0);
            ldsm4t(b20, b21, b30, b31, addr0 + 32);
            if (p1 < npairs) {
                uint32_t addr1 = wbase + ((st + 1) & 3) * STGB + boff;
                uint32_t c00, c01, c10, c11, c20, c21, c30, c31;
                ldsm4t(c00, c01, c10, c11, addr1);
                ldsm4t(c20, c21, c30, c31, addr1 + 32);
                mma16816(acc[0], cA0, zero, cA2, zero, b00, b01);
                mma16816(acc[1], cA0, zero, cA2, zero, b10, b11);
                mma16816(acc[2], cA0, zero, cA2, zero, b20, b21);
                mma16816(acc[3], cA0, zero, cA2, zero, b30, b31);
                mma16816(acc[0], cB0, zero, cB2, zero, c00, c01);
                mma16816(acc[1], cB0, zero, cB2, zero, c10, c11);
                mma16816(acc[2], cB0, zero, cB2, zero, c20, c21);
                mma16816(acc[3], cB0, zero, cB2, zero, c30, c31);
            } else {
                mma16816(acc[0], cA0, zero, cA2, zero, b00, b01);
                mma16816(acc[1], cA0, zero, cA2, zero, b10, b11);
                mma16816(acc[2], cA0, zero, cA2, zero, b20, b21);
                mma16816(acc[3], cA0, zero, cA2, zero, b30, b31);
            }
        }

        // refill stage st with pair p0+4, stage st+1 with pair p1+4 (2 commits)
        {
            int pf = p0 + NSTG;
            if (pf < npairs) {
                int j0 = 2 * pf;
                int s0 = ssrc[j0];
                int s1 = (j0 + 1 < cnt) ? ssrc[j0 + 1] : s0;
                uint32_t d = wbase + st * STGB + cpoff;
                cp16(d,            g_xTh + ((size_t)s0 * 8 + row1) * BATCH_ + gcol);
                cp16(d + 8 * ROWB, g_xTh + ((size_t)s1 * 8 + row1) * BATCH_ + gcol);
            }
            cp_commit();
            int pg = p1 + NSTG;
            if (pg < npairs) {
                int j0 = 2 * pg;
                int s0 = ssrc[j0];
                int s1 = (j0 + 1 < cnt) ? ssrc[j0 + 1] : s0;
                uint32_t d = wbase + ((st + 1) & 3) * STGB + cpoff;
                cp16(d,            g_xTh + ((size_t)s0 * 8 + row1) * BATCH_ + gcol);
                cp16(d + 8 * ROWB, g_xTh + ((size_t)s1 * 8 + row1) * BATCH_ + gcol);
            }
            cp_commit();
        }

        cA0 = nA0; cA2 = nA2; cB0 = nB0; cB2 = nB2;
        st = (st + 2) & 3;
    }

    // ---- epilogue: frags -> smem [8 o][132 b], residual, per-thread store ----
    __syncthreads();
    float* sred = (float*)sx;   // 8*132*4 = 4224 B
#pragma unroll
    for (int q = 0; q < 4; q++) {
        int o = lane >> 2;
        int b = wid * 32 + q * 8 + ((lane & 3) << 1);
        sred[o * 132 + b]     = acc[q][0];
        sred[o * 132 + b + 1] = acc[q][1];
    }
    __syncthreads();

    if (tid == 0) g_cnt[g] = 0;   // ready for next graph replay

    int b = tid;
    size_t obase = (size_t)b * D_ + (size_t)g * 8;
    float4 r0 = *(const float4*)(x + obase);
    float4 r1 = *(const float4*)(x + obase + 4);
    float s[8];
#pragma unroll
    for (int o = 0; o < 8; o++) s[o] = sred[o * 132 + b];
    float4 o0 = make_float4(r0.x + s[0], r0.y + s[1], r0.z + s[2], r0.w + s[3]);
    float4 o1 = make_float4(r1.x + s[4], r1.y + s[5], r1.z + s[6], r1.w + s[7]);
    *(float4*)(out + obase)     = o0;
    *(float4*)(out + obase + 4) = o1;
}

// ---------------- launch ----------------

extern "C" void kernel_launch(void* const* d_in, const int* in_sizes, int n_in,
                              void* d_out, int out_size) {
    const float* x  = (const float*)d_in[0];   // (128, 32000) f32
    const float* w  = (const float*)d_in[1];   // (132000, 8, 8) f32
    const int*   bi = (const int*)d_in[2];     // block_in
    const int*   bo = (const int*)d_in[3];     // block_out
    float* out = (float*)d_out;

    pre_kernel<<<4000 + SCAT_CTAS, 256>>>(x, bi, bo);
    main_kernel<<<G_, 128>>>(x, w, out);
}